// round 14
// baseline (speedup 1.0000x reference)
#include <cuda_runtime.h>
#include <math.h>

#define BB 32
#define TT 256
#define IND 64
#define DD 128

#define NSM   148
#define NPROD 32
#define NCONS (NSM - NPROD)

// output layout (floats): h_final | y | jacs | dh_dWh
#define OUT_Y   ((size_t)BB * DD)
#define OUT_JAC (OUT_Y + (size_t)BB * TT * DD)
#define OUT_DWH (OUT_JAC + (size_t)TT * BB * DD * DD)

// scratch (device globals; allocation-free rule)
__device__ float g_scr[TT * BB * DD];
__device__ float c_scr[TT * BB * DD];
__device__ float p_scr[TT * BB * DD];
__device__ float c2_scr[BB * DD];
__device__ float d2_scr[BB * DD];
__device__ volatile int progress[BB];
__device__ int p1done_cnt;

// ---------------- XLA:CPU math replicas (bit-exact path) ----------------
__device__ __forceinline__ float erf_xla_cpu(float x) {
    float w  = fminf(fmaxf(x, -4.0f), 4.0f);
    float x2 = __fmul_rn(w, w);
    float p;
    p = __fadd_rn(__fmul_rn(x2, -2.72614225801306e-10f), 2.77068142495902e-08f);
    p = __fadd_rn(__fmul_rn(x2, p), -2.10102402082508e-06f);
    p = __fadd_rn(__fmul_rn(x2, p), -5.69250639462346e-05f);
    p = __fadd_rn(__fmul_rn(x2, p), -7.34990630326855e-04f);
    p = __fadd_rn(__fmul_rn(x2, p), -2.95459980854025e-03f);
    p = __fadd_rn(__fmul_rn(x2, p), -1.60960333262415e-02f);
    p = __fmul_rn(w, p);
    float q;
    q = __fadd_rn(__fmul_rn(x2, -1.45660718464996e-05f), -2.13374055278905e-04f);
    q = __fadd_rn(__fmul_rn(x2, q), -1.68282697438203e-03f);
    q = __fadd_rn(__fmul_rn(x2, q), -7.37332916720468e-03f);
    q = __fadd_rn(__fmul_rn(x2, q), -1.42647390514189e-02f);
    return __fdiv_rn(p, q);
}

// Fast near-CR f32 exp via f64 (32-entry 2^(j/32) table + fdlibm hi/lo ln2
// reduction + degree-6 Estrin). rel err ~2^-51.
__device__ const unsigned long long EXPTAB[32] = {
    0x3ff0000000000000ULL, 0x3fefd9b0d3158574ULL, 0x3fefb5586cf9890fULL, 0x3fef9301d0125b51ULL,
    0x3fef72b83c7d517bULL, 0x3fef54873168b9aaULL, 0x3fef387a6e756238ULL, 0x3fef1e9df51fdee1ULL,
    0x3fef06fe0a31b715ULL, 0x3feef1a7373aa9cbULL, 0x3feedea64c123422ULL, 0x3feece086061892dULL,
    0x3feebfdad5362a27ULL, 0x3feeb42b569d4f82ULL, 0x3feeab07dd485429ULL, 0x3feea47eb03a5585ULL,
    0x3feea09e667f3bcdULL, 0x3fee9f75e8ec5f74ULL, 0x3feea11473eb0187ULL, 0x3feea589994cce13ULL,
    0x3feeace5422aa0dbULL, 0x3feeb737b0cdc5e5ULL, 0x3feec49182a3f090ULL, 0x3feed503b23e255dULL,
    0x3feee89f995ad3adULL, 0x3feeff76f2fb5e47ULL, 0x3fef199bdd85529cULL, 0x3fef3720dcef9069ULL,
    0x3fef5818dcfba487ULL, 0x3fef7c97337b9b5fULL, 0x3fefa4afa2a490daULL, 0x3fefd0765b6e4540ULL
};

__device__ __forceinline__ float exp_cr_fast(float xf) {
    const double Shift = 6755399441055744.0;               // 1.5 * 2^52
    double x = (double)xf;
    double z = __fma_rn(x, 0x1.71547652b82fep+5, Shift);   // x * 32/ln2 + Shift
    unsigned long long kbits = (unsigned long long)__double_as_longlong(z);
    double kd = z - Shift;
    double r  = __fma_rn(kd, -0x1.62e42feep-6, x);         // ln2_hi / 32
    r = __fma_rn(kd, -0x1.a39ef35793c76p-38, r);           // ln2_lo / 32
    unsigned long long tbits = EXPTAB[kbits & 31] + (kbits << 47);
    double s = __longlong_as_double((long long)tbits);
    double r2 = r * r;
    double A  = __fma_rn(r, 0x1.5555555555555p-3, 0.5);
    double B  = __fma_rn(r, 0x1.1111111111111p-7, 0x1.5555555555555p-5);
    double u  = r + 1.0;
    double r4 = r2 * r2;
    double C  = __fma_rn(r2, 0x1.6c16c16c16c17p-10, B);
    double P  = __fma_rn(r2, A, u);
    double e  = __fma_rn(r4, C, P);
    return (float)(e * s);
}

__device__ __forceinline__ float sigmoid_xla_cpu(float s) {
    float e = exp_cr_fast(__fmul_rn(s, -1.0f));
    return __fdiv_rn(1.0f, __fadd_rn(1.0f, e));
}

__global__ void reset_kernel() {
    int i = threadIdx.x;
    if (i < BB) progress[i] = 0;
    if (i == BB) p1done_cnt = 0;
}

#define PROD_SMEM_FLOATS (2 * DD * DD + IND * DD + DD + DD + 2 * IND)
#define CONS_SMEM_FLOATS (2 * DD * DD + 3 * DD + DD)
#define FUSED_SMEM_FLOATS (PROD_SMEM_FLOATS > CONS_SMEM_FLOATS ? PROD_SMEM_FLOATS : CONS_SMEM_FLOATS)
#define FUSED_SMEM_BYTES  (FUSED_SMEM_FLOATS * 4)
#define P2_THRESH 64

__global__ void __launch_bounds__(256, 1)
fused_kernel(const float* __restrict__ x, const float* __restrict__ h0,
             const float* __restrict__ Wx, const float* __restrict__ Wg,
             const float* __restrict__ Wh, float* __restrict__ out)
{
    extern __shared__ float sm[];
    __shared__ float vs[DD];
    __shared__ float hsh[DD];
    __shared__ int cnt;

    const int tid = threadIdx.x;
    const int bid = blockIdx.x;

    if (bid < NPROD) {
        // ================= PRODUCER: phase 1 (bit-exact XLA:CPU) =================
        float* Whs = sm;
        float* Wgs = Whs + DD * DD;
        float* Wxs = Wgs + DD * DD;
        float* hs  = Wxs + IND * DD;
        float* as_ = hs + DD;
        float* xsb = as_ + DD;                 // [2][64]

        const int b = bid;
        const int i = tid;
        const int lane = tid & 31;
        const float* xrow = x + (size_t)b * TT * IND;

        for (int idx = tid; idx < DD * DD; idx += 256) {
            Whs[idx] = Wh[idx];
            Wgs[idx] = Wg[idx];
        }
        for (int idx = tid; idx < IND * DD; idx += 256) Wxs[idx] = Wx[idx];
        if (i < IND) xsb[i] = xrow[i];
        if (i < DD) hs[i] = h0[b * DD + i];
        __syncthreads();

        float* yrow = out + OUT_Y + (size_t)b * TT * DD;
        const float SQRT2 = 1.41421356237309515f;

        for (int t = 0; t < TT; t++) {
            const bool pub = ((t & 7) == 7);
            if (tid >= 128 && tid < 128 + IND) {
                int tn = t + 1;
                if (tn < TT) xsb[((tn & 1) << 6) + (tid - 128)] = xrow[(size_t)tn * IND + (tid - 128)];
            }
            if (i < DD) {
                const float* xv = xsb + ((t & 1) << 6);
                float acc1 = 0.0f, acc2 = 0.0f;
                // k 0..63: Wx and Wh chains interleaved (each ascending-k serial)
                #pragma unroll
                for (int kb = 0; kb < IND; kb += 32) {
                    float xvv = xv[kb + lane];   // conflict-free lane load
                    float hvv = hs[kb + lane];
                    #pragma unroll
                    for (int uu = 0; uu < 32; uu += 8) {
                        float wx[8], wh[8];
                        #pragma unroll
                        for (int v = 0; v < 8; v++) {
                            wx[v] = Wxs[(kb + uu + v) * DD + i];
                            wh[v] = Whs[(kb + uu + v) * DD + i];
                        }
                        #pragma unroll
                        for (int v = 0; v < 8; v++) {
                            float xb = __shfl_sync(0xffffffffu, xvv, uu + v);
                            float hb = __shfl_sync(0xffffffffu, hvv, uu + v);
                            acc1 = fmaf(xb, wx[v], acc1);
                            acc2 = fmaf(hb, wh[v], acc2);
                        }
                    }
                }
                // k 64..127: Wh only
                #pragma unroll
                for (int kb = IND; kb < DD; kb += 32) {
                    float hvv = hs[kb + lane];
                    #pragma unroll
                    for (int uu = 0; uu < 32; uu += 8) {
                        float wh[8];
                        #pragma unroll
                        for (int v = 0; v < 8; v++) wh[v] = Whs[(kb + uu + v) * DD + i];
                        #pragma unroll
                        for (int v = 0; v < 8; v++) {
                            float hb = __shfl_sync(0xffffffffu, hvv, uu + v);
                            acc2 = fmaf(hb, wh[v], acc2);
                        }
                    }
                }
                float pre = __fadd_rn(acc1, acc2);
                float u_ = __fdiv_rn(pre, SQRT2);
                float er = erf_xla_cpu(u_);
                float a  = __fmul_rn(__fmul_rn(pre, __fadd_rn(er, 1.0f)), 0.5f);
                as_[i] = a;
                p_scr[((size_t)t * BB + b) * DD + i] = pre;
            }
            __syncthreads();

            if (i < DD) {
                float acc3 = 0.0f;
                #pragma unroll
                for (int kb = 0; kb < DD; kb += 32) {
                    float avv = as_[kb + lane];
                    #pragma unroll
                    for (int uu = 0; uu < 32; uu += 8) {
                        float w[8];
                        #pragma unroll
                        for (int v = 0; v < 8; v++) w[v] = Wgs[(kb + uu + v) * DD + i];
                        #pragma unroll
                        for (int v = 0; v < 8; v++) {
                            float ab = __shfl_sync(0xffffffffu, avv, uu + v);
                            acc3 = fmaf(ab, w[v], acc3);
                        }
                    }
                }
                float g = sigmoid_xla_cpu(acc3);
                float h = hs[i];
                float c = (h - 1.0f) * g * (1.0f - g);
                float hn = __fadd_rn(__fmul_rn(g, h), __fsub_rn(1.0f, g));

                size_t o = ((size_t)t * BB + b) * DD + i;
                g_scr[o] = g;
                c_scr[o] = c;
                yrow[(size_t)t * DD + i] = hn;
                hs[i] = hn;
                if (pub) __threadfence();
            }
            __syncthreads();
            if (pub && tid == 0) progress[b] = t + 1;
        }

        if (i < DD) out[b * DD + i] = hs[i];
        {
            // extra eval for dh_dWh (broadcast-LDS form; runs once, identical math)
            if (i < DD) {
                const float* xv = xsb + (((TT - 1) & 1) << 6);
                float acc1 = 0.0f, acc2 = 0.0f;
                #pragma unroll
                for (int kb = 0; kb < IND; kb += 8) {
                    float wx[8], xr[8], wh[8], hr[8];
                    #pragma unroll
                    for (int u = 0; u < 8; u++) {
                        wx[u] = Wxs[(kb + u) * DD + i]; xr[u] = xv[kb + u];
                        wh[u] = Whs[(kb + u) * DD + i]; hr[u] = hs[kb + u];
                    }
                    #pragma unroll
                    for (int u = 0; u < 8; u++) {
                        acc1 = fmaf(xr[u], wx[u], acc1);
                        acc2 = fmaf(hr[u], wh[u], acc2);
                    }
                }
                #pragma unroll
                for (int kb = IND; kb < DD; kb += 8) {
                    float wh[8], hr[8];
                    #pragma unroll
                    for (int u = 0; u < 8; u++) { wh[u] = Whs[(kb + u) * DD + i]; hr[u] = hs[kb + u]; }
                    #pragma unroll
                    for (int u = 0; u < 8; u++) acc2 = fmaf(hr[u], wh[u], acc2);
                }
                float pre = __fadd_rn(acc1, acc2);
                float u_ = __fdiv_rn(pre, SQRT2);
                float er = erf_xla_cpu(u_);
                float a  = __fmul_rn(__fmul_rn(pre, __fadd_rn(er, 1.0f)), 0.5f);
                float cdf = 0.5f * (1.0f + er);
                d2_scr[b * DD + i] = cdf + pre * 0.3989422804014327f * expf(-0.5f * pre * pre);
                as_[i] = a;
            }
            __syncthreads();
            if (i < DD) {
                float acc3 = 0.0f;
                #pragma unroll
                for (int kb = 0; kb < DD; kb += 8) {
                    float w[8], av[8];
                    #pragma unroll
                    for (int u = 0; u < 8; u++) { w[u] = Wgs[(kb + u) * DD + i]; av[u] = as_[kb + u]; }
                    #pragma unroll
                    for (int u = 0; u < 8; u++) acc3 = fmaf(av[u], w[u], acc3);
                }
                float g = sigmoid_xla_cpu(acc3);
                float h = hs[i];
                c2_scr[b * DD + i] = (h - 1.0f) * g * (1.0f - g);
                __threadfence();
            }
        }
        __syncthreads();
        if (tid == 0) atomicAdd(&p1done_cnt, 1);
    } else {
        // ================= CONSUMER: phase 2 =================
        float* Wgs = sm;
        float* WhT = sm + DD * DD;
        float* ds  = WhT + DD * DD;
        float* cs  = ds + DD;
        float* gs  = cs + DD;
        int* rowlist = (int*)(gs + DD);

        for (int idx = tid; idx < DD * DD; idx += 256) Wgs[idx] = Wg[idx];
        for (int idx = tid; idx < DD * DD; idx += 256) {
            int j = idx / DD, k = idx % DD;
            WhT[k * DD + j] = Wh[idx];
        }

        const int ti = tid & 15, tj = tid >> 4;
        const int i0 = ti * 8, j0 = tj * 8;
        float* jbase = out + OUT_JAC;
        const int cid = bid - NPROD;

        for (int job = cid; job < TT * BB; job += NCONS) {
            const int b = job & (BB - 1);
            const int t = job >> 5;
            if (tid == 0) {
                while (progress[b] < t + 1) __nanosleep(64);
                __threadfence();
                cnt = 0;
            }
            __syncthreads();
            if (tid < DD) {
                size_t o = (size_t)job * DD + tid;
                float pre = __ldcg(&p_scr[o]);
                float cdf = 0.5f * (1.0f + erff(pre * 0.7071067811865476f));
                ds[tid] = cdf + pre * 0.3989422804014327f * expf(-0.5f * pre * pre);
                float c = __ldcg(&c_scr[o]);
                cs[tid] = c;
                gs[tid] = __ldcg(&g_scr[o]);
                if (c != 0.0f) { int p = atomicAdd(&cnt, 1); rowlist[p] = tid; }
            }
            __syncthreads();
            int n = cnt;
            float* jac = jbase + (size_t)job * (DD * DD);

            if (n > P2_THRESH) {
                float acc[8][8];
                #pragma unroll
                for (int a = 0; a < 8; a++)
                    #pragma unroll
                    for (int q = 0; q < 8; q++) acc[a][q] = 0.f;

                #pragma unroll 2
                for (int k = 0; k < DD; k++) {
                    float dk = ds[k];
                    float4 wa0 = *(const float4*)(Wgs + k * DD + i0);
                    float4 wa1 = *(const float4*)(Wgs + k * DD + i0 + 4);
                    float4 wb0 = *(const float4*)(WhT + k * DD + j0);
                    float4 wb1 = *(const float4*)(WhT + k * DD + j0 + 4);
                    float av[8] = {wa0.x * dk, wa0.y * dk, wa0.z * dk, wa0.w * dk,
                                   wa1.x * dk, wa1.y * dk, wa1.z * dk, wa1.w * dk};
                    float bv[8] = {wb0.x, wb0.y, wb0.z, wb0.w, wb1.x, wb1.y, wb1.z, wb1.w};
                    #pragma unroll
                    for (int a = 0; a < 8; a++)
                        #pragma unroll
                        for (int q = 0; q < 8; q++)
                            acc[a][q] = fmaf(av[a], bv[q], acc[a][q]);
                }

                #pragma unroll
                for (int a = 0; a < 8; a++) {
                    int irow = i0 + a;
                    float ci = cs[irow], gi = gs[irow];
                    float v[8];
                    #pragma unroll
                    for (int q = 0; q < 8; q++) {
                        float val = ci * acc[a][q];
                        if (irow == j0 + q) val += gi;
                        v[q] = val;
                    }
                    float* dst = jac + (size_t)irow * DD + j0;
                    *(float4*)(dst)     = make_float4(v[0], v[1], v[2], v[3]);
                    *(float4*)(dst + 4) = make_float4(v[4], v[5], v[6], v[7]);
                }
            } else {
                float4* j4 = (float4*)jac;
                #pragma unroll 4
                for (int idx = tid; idx < DD * DD / 4; idx += 256) {
                    int row = idx >> 5;
                    if (cs[row] == 0.0f) {
                        int c0 = (idx & 31) << 2;
                        float gv = gs[row];
                        float4 v;
                        v.x = (row == c0 + 0) ? gv : 0.f;
                        v.y = (row == c0 + 1) ? gv : 0.f;
                        v.z = (row == c0 + 2) ? gv : 0.f;
                        v.w = (row == c0 + 3) ? gv : 0.f;
                        j4[idx] = v;
                    }
                }
                for (int r = 0; r < n; r += 2) {
                    int rr = r + (tid >> 7);
                    if (rr < n) {
                        int irow = rowlist[rr];
                        int j = tid & 127;
                        float a0 = 0.f, a1 = 0.f;
                        #pragma unroll 4
                        for (int k = 0; k < DD; k += 2) {
                            a0 = fmaf(ds[k]     * Wgs[k * DD + irow],       WhT[k * DD + j],       a0);
                            a1 = fmaf(ds[k + 1] * Wgs[(k + 1) * DD + irow], WhT[(k + 1) * DD + j], a1);
                        }
                        float val = cs[irow] * (a0 + a1);
                        if (irow == j) val += gs[irow];
                        jac[(size_t)irow * DD + j] = val;
                    }
                }
            }
        }
    }

    // ================= TAIL: phase 3 (all blocks) =================
    __syncthreads();
    if (tid == 0) {
        while (*(volatile int*)&p1done_cnt < NPROD) __nanosleep(128);
        __threadfence();
    }
    __syncthreads();

    for (int bi = bid; bi < BB * DD; bi += NSM) {
        const int b = bi >> 7, i = bi & 127;
        if (tid < DD) {
            float c2 = __ldcg(&c2_scr[b * DD + i]);
            vs[tid]  = c2 * __ldcg(&d2_scr[b * DD + tid]) * Wg[tid * DD + i];
            hsh[tid] = __ldcg(&out[b * DD + tid]);
        }
        __syncthreads();
        float4* dst = (float4*)(out + OUT_DWH + (size_t)bi * DD * DD);
        const float4* vs4 = (const float4*)vs;
        #pragma unroll 4
        for (int idx = tid; idx < DD * DD / 4; idx += 256) {
            int p  = idx >> 5;
            int q4 = idx & 31;
            float hp = hsh[p];
            float4 v = vs4[q4];
            dst[idx] = make_float4(v.x * hp, v.y * hp, v.z * hp, v.w * hp);
        }
        __syncthreads();
    }
}

extern "C" void kernel_launch(void* const* d_in, const int* in_sizes, int n_in,
                              void* d_out, int out_size) {
    const float* x  = (const float*)d_in[0];
    const float* h0 = (const float*)d_in[1];
    const float* Wx = (const float*)d_in[2];
    const float* Wg = (const float*)d_in[3];
    const float* Wh = (const float*)d_in[4];
    float* out = (float*)d_out;

    cudaFuncSetAttribute(fused_kernel, cudaFuncAttributeMaxDynamicSharedMemorySize, FUSED_SMEM_BYTES);

    reset_kernel<<<1, 64>>>();
    fused_kernel<<<NSM, 256, FUSED_SMEM_BYTES>>>(x, h0, Wx, Wg, Wh, out);
}

// round 16
// speedup vs baseline: 1.0633x; 1.0633x over previous
#include <cuda_runtime.h>
#include <math.h>

#define BB 32
#define TT 256
#define IND 64
#define DD 128

#define NSM   148
#define NPROD 32
#define NCONS (NSM - NPROD)

// output layout (floats): h_final | y | jacs | dh_dWh
#define OUT_Y   ((size_t)BB * DD)
#define OUT_JAC (OUT_Y + (size_t)BB * TT * DD)
#define OUT_DWH (OUT_JAC + (size_t)TT * BB * DD * DD)

// scratch (device globals; allocation-free rule)
__device__ float g_scr[TT * BB * DD];
__device__ float c_scr[TT * BB * DD];
__device__ float p_scr[TT * BB * DD];
__device__ float c2_scr[BB * DD];
__device__ float d2_scr[BB * DD];
__device__ volatile int progress[BB];
__device__ int p1done_cnt;

// ---------------- XLA:CPU math replicas (bit-exact path — DO NOT TOUCH) ----------------
__device__ __forceinline__ float erf_xla_cpu(float x) {
    float w  = fminf(fmaxf(x, -4.0f), 4.0f);
    float x2 = __fmul_rn(w, w);
    float p;
    p = __fadd_rn(__fmul_rn(x2, -2.72614225801306e-10f), 2.77068142495902e-08f);
    p = __fadd_rn(__fmul_rn(x2, p), -2.10102402082508e-06f);
    p = __fadd_rn(__fmul_rn(x2, p), -5.69250639462346e-05f);
    p = __fadd_rn(__fmul_rn(x2, p), -7.34990630326855e-04f);
    p = __fadd_rn(__fmul_rn(x2, p), -2.95459980854025e-03f);
    p = __fadd_rn(__fmul_rn(x2, p), -1.60960333262415e-02f);
    p = __fmul_rn(w, p);
    float q;
    q = __fadd_rn(__fmul_rn(x2, -1.45660718464996e-05f), -2.13374055278905e-04f);
    q = __fadd_rn(__fmul_rn(x2, q), -1.68282697438203e-03f);
    q = __fadd_rn(__fmul_rn(x2, q), -7.37332916720468e-03f);
    q = __fadd_rn(__fmul_rn(x2, q), -1.42647390514189e-02f);
    return __fdiv_rn(p, q);
}

// Fast near-CR f32 exp via f64 (32-entry 2^(j/32) table + fdlibm hi/lo ln2
// reduction + degree-6 Estrin). Proven bit-compatible in R13/R14.
__device__ const unsigned long long EXPTAB[32] = {
    0x3ff0000000000000ULL, 0x3fefd9b0d3158574ULL, 0x3fefb5586cf9890fULL, 0x3fef9301d0125b51ULL,
    0x3fef72b83c7d517bULL, 0x3fef54873168b9aaULL, 0x3fef387a6e756238ULL, 0x3fef1e9df51fdee1ULL,
    0x3fef06fe0a31b715ULL, 0x3feef1a7373aa9cbULL, 0x3feedea64c123422ULL, 0x3feece086061892dULL,
    0x3feebfdad5362a27ULL, 0x3feeb42b569d4f82ULL, 0x3feeab07dd485429ULL, 0x3feea47eb03a5585ULL,
    0x3feea09e667f3bcdULL, 0x3fee9f75e8ec5f74ULL, 0x3feea11473eb0187ULL, 0x3feea589994cce13ULL,
    0x3feeace5422aa0dbULL, 0x3feeb737b0cdc5e5ULL, 0x3feec49182a3f090ULL, 0x3feed503b23e255dULL,
    0x3feee89f995ad3adULL, 0x3feeff76f2fb5e47ULL, 0x3fef199bdd85529cULL, 0x3fef3720dcef9069ULL,
    0x3fef5818dcfba487ULL, 0x3fef7c97337b9b5fULL, 0x3fefa4afa2a490daULL, 0x3fefd0765b6e4540ULL
};

__device__ __forceinline__ float exp_cr_fast(float xf) {
    const double Shift = 6755399441055744.0;               // 1.5 * 2^52
    double x = (double)xf;
    double z = __fma_rn(x, 0x1.71547652b82fep+5, Shift);   // x * 32/ln2 + Shift
    unsigned long long kbits = (unsigned long long)__double_as_longlong(z);
    double kd = z - Shift;
    double r  = __fma_rn(kd, -0x1.62e42feep-6, x);         // ln2_hi / 32
    r = __fma_rn(kd, -0x1.a39ef35793c76p-38, r);           // ln2_lo / 32
    unsigned long long tbits = EXPTAB[kbits & 31] + (kbits << 47);
    double s = __longlong_as_double((long long)tbits);
    double r2 = r * r;
    double A  = __fma_rn(r, 0x1.5555555555555p-3, 0.5);
    double B  = __fma_rn(r, 0x1.1111111111111p-7, 0x1.5555555555555p-5);
    double u  = r + 1.0;
    double r4 = r2 * r2;
    double C  = __fma_rn(r2, 0x1.6c16c16c16c17p-10, B);
    double P  = __fma_rn(r2, A, u);
    double e  = __fma_rn(r4, C, P);
    return (float)(e * s);
}

__device__ __forceinline__ float sigmoid_xla_cpu(float s) {
    float e = exp_cr_fast(__fmul_rn(s, -1.0f));
    return __fdiv_rn(1.0f, __fadd_rn(1.0f, e));
}

__global__ void reset_kernel() {
    int i = threadIdx.x;
    if (i < BB) progress[i] = 0;
    if (i == BB) p1done_cnt = 0;
}

// producer smem layout (floats):
//   hs[128] | as[128] | xsb[2][64] | WxT[128][68] | WgT[128][132]
#define P_HS   0
#define P_AS   (P_HS + DD)
#define P_XSB  (P_AS + DD)
#define P_WXT  (P_XSB + 2 * IND)
#define P_WGT  (P_WXT + DD * 68)
#define PROD_SMEM_FLOATS (P_WGT + DD * 132)
#define CONS_SMEM_FLOATS (2 * DD * DD + 3 * DD + DD)
#define FUSED_SMEM_FLOATS (PROD_SMEM_FLOATS > CONS_SMEM_FLOATS ? PROD_SMEM_FLOATS : CONS_SMEM_FLOATS)
#define FUSED_SMEM_BYTES  (FUSED_SMEM_FLOATS * 4)
#define P2_THRESH 64

__global__ void __launch_bounds__(256, 1)
fused_kernel(const float* __restrict__ x, const float* __restrict__ h0,
             const float* __restrict__ Wx, const float* __restrict__ Wg,
             const float* __restrict__ Wh, float* __restrict__ out)
{
    extern __shared__ float sm[];
    __shared__ float vs[DD];
    __shared__ float hsh[DD];
    __shared__ int cnt;

    const int tid = threadIdx.x;
    const int bid = blockIdx.x;

    if (bid < NPROD) {
        // ===== PRODUCER: phase 1, one thread/element, serial ascending-k chains =====
        float* hs  = sm + P_HS;
        float* as_ = sm + P_AS;
        float* xsb = sm + P_XSB;           // [2][64]
        float* WxT = sm + P_WXT;           // [i][k], pad 68
        float* WgT = sm + P_WGT;           // [i][k], pad 132

        const int b = bid;
        const int i = tid;                 // threads 0..127 compute element i
        const float* xrow = x + (size_t)b * TT * IND;

        // transposed weight staging (conflict pattern: 68%32==4, 132%32==4 -> 4-phase)
        for (int idx = tid; idx < IND * DD; idx += 256) {
            int k = idx / DD, col = idx % DD;
            WxT[col * 68 + k] = Wx[idx];
        }
        for (int idx = tid; idx < DD * DD; idx += 256) {
            int k = idx / DD, col = idx % DD;
            WgT[col * 132 + k] = Wg[idx];
        }
        // Wh column -> registers (private per thread)
        float whreg[DD];
        if (i < DD) {
            #pragma unroll
            for (int k = 0; k < DD; k++) whreg[k] = Wh[k * DD + i];
        }
        if (tid < IND) xsb[tid] = xrow[tid];
        if (i < DD) hs[i] = h0[b * DD + i];
        __syncthreads();

        float* yrow = out + OUT_Y + (size_t)b * TT * DD;
        const float SQRT2 = 1.41421356237309515f;

        const float4* wx4 = (const float4*)(WxT + (i < DD ? i : 0) * 68);
        const float4* wg4 = (const float4*)(WgT + (i < DD ? i : 0) * 132);
        const float4* hs4 = (const float4*)hs;
        const float4* as4 = (const float4*)as_;

        for (int t = 0; t < TT; t++) {
            const bool pub = ((t & 7) == 7);
            // prefetch next x (warps 4-5), write into the other buffer (no hazard:
            // that buffer's readers finished in step t-1 before its last barrier)
            if (tid >= 128 && tid < 128 + IND && t + 1 < TT)
                xsb[(((t + 1) & 1) << 6) + (tid - 128)] = xrow[(size_t)(t + 1) * IND + (tid - 128)];

            if (i < DD) {
                const float4* xv4 = (const float4*)(xsb + ((t & 1) << 6));
                // acc1 = serial ascending chain x @ Wx (float4 loads, scalar chain)
                float acc1 = 0.0f;
                #pragma unroll
                for (int q = 0; q < IND / 4; q++) {
                    float4 xv = xv4[q];
                    float4 wv = wx4[q];
                    acc1 = fmaf(xv.x, wv.x, acc1);
                    acc1 = fmaf(xv.y, wv.y, acc1);
                    acc1 = fmaf(xv.z, wv.z, acc1);
                    acc1 = fmaf(xv.w, wv.w, acc1);
                }
                // acc2 = serial ascending chain h @ Wh (register weights)
                float acc2 = 0.0f;
                #pragma unroll
                for (int q = 0; q < DD / 4; q++) {
                    float4 hv = hs4[q];
                    acc2 = fmaf(hv.x, whreg[4 * q + 0], acc2);
                    acc2 = fmaf(hv.y, whreg[4 * q + 1], acc2);
                    acc2 = fmaf(hv.z, whreg[4 * q + 2], acc2);
                    acc2 = fmaf(hv.w, whreg[4 * q + 3], acc2);
                }
                float pre = __fadd_rn(acc1, acc2);
                float u_  = __fdiv_rn(pre, SQRT2);
                float er  = erf_xla_cpu(u_);
                float a   = __fmul_rn(__fmul_rn(pre, __fadd_rn(er, 1.0f)), 0.5f);
                as_[i] = a;
                p_scr[((size_t)t * BB + b) * DD + i] = pre;
            }
            __syncthreads();                    // B2: as ready; hs reads done

            if (i < DD) {
                // acc3 = serial ascending chain a @ Wgate (float4 smem weights)
                float acc3 = 0.0f;
                #pragma unroll
                for (int q = 0; q < DD / 4; q++) {
                    float4 av = as4[q];
                    float4 wv = wg4[q];
                    acc3 = fmaf(av.x, wv.x, acc3);
                    acc3 = fmaf(av.y, wv.y, acc3);
                    acc3 = fmaf(av.z, wv.z, acc3);
                    acc3 = fmaf(av.w, wv.w, acc3);
                }
                float g = sigmoid_xla_cpu(acc3);
                float h = hs[i];
                float c = (h - 1.0f) * g * (1.0f - g);
                float hn = __fadd_rn(__fmul_rn(g, h), __fsub_rn(1.0f, g));

                size_t o = ((size_t)t * BB + b) * DD + i;
                g_scr[o] = g;
                c_scr[o] = c;
                yrow[(size_t)t * DD + i] = hn;
                hs[i] = hn;
                if (pub) __threadfence();
            }
            __syncthreads();                    // B4: hs + next-x published
            if (pub && tid == 0) progress[b] = t + 1;
        }

        if (i < DD) out[b * DD + i] = hs[i];

        // extra eval for dh_dWh (identical structure; x = x[:,T-1])
        {
            if (i < DD) {
                const float4* xv4 = (const float4*)(xsb + (((TT - 1) & 1) << 6));
                float acc1 = 0.0f;
                #pragma unroll
                for (int q = 0; q < IND / 4; q++) {
                    float4 xv = xv4[q];
                    float4 wv = wx4[q];
                    acc1 = fmaf(xv.x, wv.x, acc1);
                    acc1 = fmaf(xv.y, wv.y, acc1);
                    acc1 = fmaf(xv.z, wv.z, acc1);
                    acc1 = fmaf(xv.w, wv.w, acc1);
                }
                float acc2 = 0.0f;
                #pragma unroll
                for (int q = 0; q < DD / 4; q++) {
                    float4 hv = hs4[q];
                    acc2 = fmaf(hv.x, whreg[4 * q + 0], acc2);
                    acc2 = fmaf(hv.y, whreg[4 * q + 1], acc2);
                    acc2 = fmaf(hv.z, whreg[4 * q + 2], acc2);
                    acc2 = fmaf(hv.w, whreg[4 * q + 3], acc2);
                }
                float pre = __fadd_rn(acc1, acc2);
                float u_  = __fdiv_rn(pre, SQRT2);
                float er  = erf_xla_cpu(u_);
                float a   = __fmul_rn(__fmul_rn(pre, __fadd_rn(er, 1.0f)), 0.5f);
                float cdf = 0.5f * (1.0f + er);
                d2_scr[b * DD + i] = cdf + pre * 0.3989422804014327f * expf(-0.5f * pre * pre);
                as_[i] = a;
            }
            __syncthreads();
            if (i < DD) {
                float acc3 = 0.0f;
                #pragma unroll
                for (int q = 0; q < DD / 4; q++) {
                    float4 av = as4[q];
                    float4 wv = wg4[q];
                    acc3 = fmaf(av.x, wv.x, acc3);
                    acc3 = fmaf(av.y, wv.y, acc3);
                    acc3 = fmaf(av.z, wv.z, acc3);
                    acc3 = fmaf(av.w, wv.w, acc3);
                }
                float g = sigmoid_xla_cpu(acc3);
                float h = hs[i];
                c2_scr[b * DD + i] = (h - 1.0f) * g * (1.0f - g);
                __threadfence();
            }
        }
        __syncthreads();
        if (tid == 0) atomicAdd(&p1done_cnt, 1);
    } else {
        // ================= CONSUMER: phase 2 (unchanged from R13) =================
        float* Wgs = sm;
        float* WhT = sm + DD * DD;
        float* ds  = WhT + DD * DD;
        float* cs  = ds + DD;
        float* gs  = cs + DD;
        int* rowlist = (int*)(gs + DD);

        for (int idx = tid; idx < DD * DD; idx += 256) Wgs[idx] = Wg[idx];
        for (int idx = tid; idx < DD * DD; idx += 256) {
            int j = idx / DD, k = idx % DD;
            WhT[k * DD + j] = Wh[idx];
        }

        const int ti = tid & 15, tj = tid >> 4;
        const int i0 = ti * 8, j0 = tj * 8;
        float* jbase = out + OUT_JAC;
        const int cid = bid - NPROD;

        for (int job = cid; job < TT * BB; job += NCONS) {
            const int b = job & (BB - 1);
            const int t = job >> 5;
            if (tid == 0) {
                while (progress[b] < t + 1) __nanosleep(64);
                __threadfence();
                cnt = 0;
            }
            __syncthreads();
            if (tid < DD) {
                size_t o = (size_t)job * DD + tid;
                float pre = __ldcg(&p_scr[o]);
                float cdf = 0.5f * (1.0f + erff(pre * 0.7071067811865476f));
                ds[tid] = cdf + pre * 0.3989422804014327f * expf(-0.5f * pre * pre);
                float c = __ldcg(&c_scr[o]);
                cs[tid] = c;
                gs[tid] = __ldcg(&g_scr[o]);
                if (c != 0.0f) { int p = atomicAdd(&cnt, 1); rowlist[p] = tid; }
            }
            __syncthreads();
            int n = cnt;
            float* jac = jbase + (size_t)job * (DD * DD);

            if (n > P2_THRESH) {
                float acc[8][8];
                #pragma unroll
                for (int a = 0; a < 8; a++)
                    #pragma unroll
                    for (int q = 0; q < 8; q++) acc[a][q] = 0.f;

                #pragma unroll 2
                for (int k = 0; k < DD; k++) {
                    float dk = ds[k];
                    float4 wa0 = *(const float4*)(Wgs + k * DD + i0);
                    float4 wa1 = *(const float4*)(Wgs + k * DD + i0 + 4);
                    float4 wb0 = *(const float4*)(WhT + k * DD + j0);
                    float4 wb1 = *(const float4*)(WhT + k * DD + j0 + 4);
                    float av[8] = {wa0.x * dk, wa0.y * dk, wa0.z * dk, wa0.w * dk,
                                   wa1.x * dk, wa1.y * dk, wa1.z * dk, wa1.w * dk};
                    float bv[8] = {wb0.x, wb0.y, wb0.z, wb0.w, wb1.x, wb1.y, wb1.z, wb1.w};
                    #pragma unroll
                    for (int a = 0; a < 8; a++)
                        #pragma unroll
                        for (int q = 0; q < 8; q++)
                            acc[a][q] = fmaf(av[a], bv[q], acc[a][q]);
                }

                #pragma unroll
                for (int a = 0; a < 8; a++) {
                    int irow = i0 + a;
                    float ci = cs[irow], gi = gs[irow];
                    float v[8];
                    #pragma unroll
                    for (int q = 0; q < 8; q++) {
                        float val = ci * acc[a][q];
                        if (irow == j0 + q) val += gi;
                        v[q] = val;
                    }
                    float* dst = jac + (size_t)irow * DD + j0;
                    *(float4*)(dst)     = make_float4(v[0], v[1], v[2], v[3]);
                    *(float4*)(dst + 4) = make_float4(v[4], v[5], v[6], v[7]);
                }
            } else {
                float4* j4 = (float4*)jac;
                #pragma unroll 4
                for (int idx = tid; idx < DD * DD / 4; idx += 256) {
                    int row = idx >> 5;
                    if (cs[row] == 0.0f) {
                        int c0 = (idx & 31) << 2;
                        float gv = gs[row];
                        float4 v;
                        v.x = (row == c0 + 0) ? gv : 0.f;
                        v.y = (row == c0 + 1) ? gv : 0.f;
                        v.z = (row == c0 + 2) ? gv : 0.f;
                        v.w = (row == c0 + 3) ? gv : 0.f;
                        j4[idx] = v;
                    }
                }
                for (int r = 0; r < n; r += 2) {
                    int rr = r + (tid >> 7);
                    if (rr < n) {
                        int irow = rowlist[rr];
                        int j = tid & 127;
                        float a0 = 0.f, a1 = 0.f;
                        #pragma unroll 4
                        for (int k = 0; k < DD; k += 2) {
                            a0 = fmaf(ds[k]     * Wgs[k * DD + irow],       WhT[k * DD + j],       a0);
                            a1 = fmaf(ds[k + 1] * Wgs[(k + 1) * DD + irow], WhT[(k + 1) * DD + j], a1);
                        }
                        float val = cs[irow] * (a0 + a1);
                        if (irow == j) val += gs[irow];
                        jac[(size_t)irow * DD + j] = val;
                    }
                }
            }
        }
    }

    // ================= TAIL: phase 3 (all blocks) =================
    __syncthreads();
    if (tid == 0) {
        while (*(volatile int*)&p1done_cnt < NPROD) __nanosleep(128);
        __threadfence();
    }
    __syncthreads();

    for (int bi = bid; bi < BB * DD; bi += NSM) {
        const int b = bi >> 7, i = bi & 127;
        if (tid < DD) {
            float c2 = __ldcg(&c2_scr[b * DD + i]);
            vs[tid]  = c2 * __ldcg(&d2_scr[b * DD + tid]) * Wg[tid * DD + i];
            hsh[tid] = __ldcg(&out[b * DD + tid]);
        }
        __syncthreads();
        float4* dst = (float4*)(out + OUT_DWH + (size_t)bi * DD * DD);
        const float4* vs4 = (const float4*)vs;
        #pragma unroll 4
        for (int idx = tid; idx < DD * DD / 4; idx += 256) {
            int p  = idx >> 5;
            int q4 = idx & 31;
            float hp = hsh[p];
            float4 v = vs4[q4];
            dst[idx] = make_float4(v.x * hp, v.y * hp, v.z * hp, v.w * hp);
        }
        __syncthreads();
    }
}

extern "C" void kernel_launch(void* const* d_in, const int* in_sizes, int n_in,
                              void* d_out, int out_size) {
    const float* x  = (const float*)d_in[0];
    const float* h0 = (const float*)d_in[1];
    const float* Wx = (const float*)d_in[2];
    const float* Wg = (const float*)d_in[3];
    const float* Wh = (const float*)d_in[4];
    float* out = (float*)d_out;

    cudaFuncSetAttribute(fused_kernel, cudaFuncAttributeMaxDynamicSharedMemorySize, FUSED_SMEM_BYTES);

    reset_kernel<<<1, 64>>>();
    fused_kernel<<<NSM, 256, FUSED_SMEM_BYTES>>>(x, h0, Wx, Wg, Wh, out);
}

// round 17
// speedup vs baseline: 1.0652x; 1.0017x over previous
#include <cuda_runtime.h>
#include <math.h>

#define BB 32
#define TT 256
#define IND 64
#define DD 128

#define NSM   148
#define NPROD 32
#define NCONS (NSM - NPROD)

// output layout (floats): h_final | y | jacs | dh_dWh
#define OUT_Y   ((size_t)BB * DD)
#define OUT_JAC (OUT_Y + (size_t)BB * TT * DD)
#define OUT_DWH (OUT_JAC + (size_t)TT * BB * DD * DD)

// scratch (device globals; allocation-free rule)
__device__ float g_scr[TT * BB * DD];
__device__ float c_scr[TT * BB * DD];
__device__ float p_scr[TT * BB * DD];
__device__ float c2_scr[BB * DD];
__device__ float d2_scr[BB * DD];
__device__ volatile int progress[BB];
__device__ int p1done_cnt;

// ---------------- XLA:CPU math replicas (bit-exact path — DO NOT TOUCH) ----------------
__device__ __forceinline__ float erf_xla_cpu(float x) {
    float w  = fminf(fmaxf(x, -4.0f), 4.0f);
    float x2 = __fmul_rn(w, w);
    float p;
    p = __fadd_rn(__fmul_rn(x2, -2.72614225801306e-10f), 2.77068142495902e-08f);
    p = __fadd_rn(__fmul_rn(x2, p), -2.10102402082508e-06f);
    p = __fadd_rn(__fmul_rn(x2, p), -5.69250639462346e-05f);
    p = __fadd_rn(__fmul_rn(x2, p), -7.34990630326855e-04f);
    p = __fadd_rn(__fmul_rn(x2, p), -2.95459980854025e-03f);
    p = __fadd_rn(__fmul_rn(x2, p), -1.60960333262415e-02f);
    p = __fmul_rn(w, p);
    float q;
    q = __fadd_rn(__fmul_rn(x2, -1.45660718464996e-05f), -2.13374055278905e-04f);
    q = __fadd_rn(__fmul_rn(x2, q), -1.68282697438203e-03f);
    q = __fadd_rn(__fmul_rn(x2, q), -7.37332916720468e-03f);
    q = __fadd_rn(__fmul_rn(x2, q), -1.42647390514189e-02f);
    return __fdiv_rn(p, q);
}

// Fast near-CR f32 exp via f64 (32-entry 2^(j/32) table + fdlibm hi/lo ln2
// reduction + degree-6 Estrin). Proven bit-compatible R13/R14/R16.
__device__ const unsigned long long EXPTAB[32] = {
    0x3ff0000000000000ULL, 0x3fefd9b0d3158574ULL, 0x3fefb5586cf9890fULL, 0x3fef9301d0125b51ULL,
    0x3fef72b83c7d517bULL, 0x3fef54873168b9aaULL, 0x3fef387a6e756238ULL, 0x3fef1e9df51fdee1ULL,
    0x3fef06fe0a31b715ULL, 0x3feef1a7373aa9cbULL, 0x3feedea64c123422ULL, 0x3feece086061892dULL,
    0x3feebfdad5362a27ULL, 0x3feeb42b569d4f82ULL, 0x3feeab07dd485429ULL, 0x3feea47eb03a5585ULL,
    0x3feea09e667f3bcdULL, 0x3fee9f75e8ec5f74ULL, 0x3feea11473eb0187ULL, 0x3feea589994cce13ULL,
    0x3feeace5422aa0dbULL, 0x3feeb737b0cdc5e5ULL, 0x3feec49182a3f090ULL, 0x3feed503b23e255dULL,
    0x3feee89f995ad3adULL, 0x3feeff76f2fb5e47ULL, 0x3fef199bdd85529cULL, 0x3fef3720dcef9069ULL,
    0x3fef5818dcfba487ULL, 0x3fef7c97337b9b5fULL, 0x3fefa4afa2a490daULL, 0x3fefd0765b6e4540ULL
};

__device__ __forceinline__ float exp_cr_fast(float xf) {
    const double Shift = 6755399441055744.0;               // 1.5 * 2^52
    double x = (double)xf;
    double z = __fma_rn(x, 0x1.71547652b82fep+5, Shift);   // x * 32/ln2 + Shift
    unsigned long long kbits = (unsigned long long)__double_as_longlong(z);
    double kd = z - Shift;
    double r  = __fma_rn(kd, -0x1.62e42feep-6, x);         // ln2_hi / 32
    r = __fma_rn(kd, -0x1.a39ef35793c76p-38, r);           // ln2_lo / 32
    unsigned long long tbits = EXPTAB[kbits & 31] + (kbits << 47);
    double s = __longlong_as_double((long long)tbits);
    double r2 = r * r;
    double A  = __fma_rn(r, 0x1.5555555555555p-3, 0.5);
    double B  = __fma_rn(r, 0x1.1111111111111p-7, 0x1.5555555555555p-5);
    double u  = r + 1.0;
    double r4 = r2 * r2;
    double C  = __fma_rn(r2, 0x1.6c16c16c16c17p-10, B);
    double P  = __fma_rn(r2, A, u);
    double e  = __fma_rn(r4, C, P);
    return (float)(e * s);
}

__device__ __forceinline__ float sigmoid_xla_cpu(float s) {
    float e = exp_cr_fast(__fmul_rn(s, -1.0f));
    return __fdiv_rn(1.0f, __fadd_rn(1.0f, e));
}

__device__ __forceinline__ float dot4(float4 w, float4 v, float acc) {
    acc = fmaf(w.x, v.x, acc);
    acc = fmaf(w.y, v.y, acc);
    acc = fmaf(w.z, v.z, acc);
    acc = fmaf(w.w, v.w, acc);
    return acc;
}

#define WG4(base) make_float4(wreg[(base)], wreg[(base) + 1], wreg[(base) + 2], wreg[(base) + 3])

__global__ void reset_kernel() {
    int i = threadIdx.x;
    if (i < BB) progress[i] = 0;
    if (i == BB) p1done_cnt = 0;
}

// producer smem: hs[128] | as[128] | xsb[2][64] | part[256] | part2[256]
#define P_HS    0
#define P_AS    DD
#define P_XSB   (2 * DD)
#define P_PART  (2 * DD + 2 * IND)
#define P_PART2 (P_PART + 256)
#define PROD_SMEM_FLOATS (P_PART2 + 256)
#define CONS_SMEM_FLOATS (2 * DD * DD + 3 * DD + DD)
#define FUSED_SMEM_FLOATS (PROD_SMEM_FLOATS > CONS_SMEM_FLOATS ? PROD_SMEM_FLOATS : CONS_SMEM_FLOATS)
#define FUSED_SMEM_BYTES  (FUSED_SMEM_FLOATS * 4)
#define P2_THRESH 64

__global__ void __launch_bounds__(256, 1)
fused_kernel(const float* __restrict__ x, const float* __restrict__ h0,
             const float* __restrict__ Wx, const float* __restrict__ Wg,
             const float* __restrict__ Wh, float* __restrict__ out)
{
    extern __shared__ float sm[];
    __shared__ float vs[DD];
    __shared__ float hsh[DD];
    __shared__ int cnt;

    const int tid = threadIdx.x;
    const int bid = blockIdx.x;

    if (bid < NPROD) {
        // ===== PRODUCER: phase 1, R3 split-dot structure (pattern-equivalent),
        //       R10+ scalar math (bit-proven), weights in registers =====
        float* hs    = sm + P_HS;
        float* as_   = sm + P_AS;
        float* xsb   = sm + P_XSB;        // [2][64]
        float* part  = sm + P_PART;       // [256]
        float* part2 = sm + P_PART2;      // [256]

        const int b = bid;
        const int i = tid & 127;
        const int half = tid >> 7;
        const float* xrow = x + (size_t)b * TT * IND;

        // weight registers:
        //  half0: wreg[0:64]=Wx[k][i] k0..63, wreg[64:96]=Wh[k][i] k0..31, wreg[96:160]=Wg[k][i] k0..63
        //  half1: wreg[0:96]=Wh[k][i] k32..127,                      wreg[96:160]=Wg[k][i] k64..127
        float wreg[160];
        if (half == 0) {
            #pragma unroll
            for (int k = 0; k < 64; k++) wreg[k] = Wx[k * DD + i];
            #pragma unroll
            for (int k = 0; k < 32; k++) wreg[64 + k] = Wh[k * DD + i];
            #pragma unroll
            for (int k = 0; k < 64; k++) wreg[96 + k] = Wg[k * DD + i];
        } else {
            #pragma unroll
            for (int k = 0; k < 96; k++) wreg[k] = Wh[(32 + k) * DD + i];
            #pragma unroll
            for (int k = 0; k < 64; k++) wreg[96 + k] = Wg[(64 + k) * DD + i];
        }
        if (tid < IND) xsb[tid] = xrow[tid];
        if (half == 0) hs[i] = h0[b * DD + i];
        __syncthreads();

        float* yrow = out + OUT_Y + (size_t)b * TT * DD;
        const float SQRT2 = 1.41421356237309515f;
        const float4* hs4 = (const float4*)hs;
        const float4* as4 = (const float4*)as_;

        for (int t = 0; t < TT; t++) {
            const bool pub = ((t & 7) == 7);
            float xpre = 0.0f;
            const bool pf = (tid < IND) && (t + 1 < TT);
            if (pf) xpre = xrow[(size_t)(t + 1) * IND + tid];

            // ---- dot1: pre partials (R3 split: half0 = x@Wx + Wh[0:32); half1 = Wh[32:128)) ----
            {
                const float4* xv4 = (const float4*)(xsb + ((t & 1) << 6));
                float p0 = 0.f, p1 = 0.f;
                if (half == 0) {
                    #pragma unroll
                    for (int k4 = 0; k4 < 16; k4 += 2) {
                        p0 = dot4(WG4(4 * k4),     xv4[k4],     p0);
                        p1 = dot4(WG4(4 * k4 + 4), xv4[k4 + 1], p1);
                    }
                    #pragma unroll
                    for (int k4 = 0; k4 < 8; k4 += 2) {
                        p0 = dot4(WG4(64 + 4 * k4),     hs4[k4],     p0);
                        p1 = dot4(WG4(64 + 4 * k4 + 4), hs4[k4 + 1], p1);
                    }
                } else {
                    #pragma unroll
                    for (int k4 = 0; k4 < 24; k4 += 2) {
                        p0 = dot4(WG4(4 * k4),     hs4[8 + k4],     p0);
                        p1 = dot4(WG4(4 * k4 + 4), hs4[8 + k4 + 1], p1);
                    }
                }
                part[tid] = p0 + p1;
            }
            __syncthreads();                               // B1: partials ready

            if (half == 0) {
                float pre = part[i] + part[i + 128];
                float u_  = __fdiv_rn(pre, SQRT2);
                float er  = erf_xla_cpu(u_);
                float a   = __fmul_rn(__fmul_rn(pre, __fadd_rn(er, 1.0f)), 0.5f);
                as_[i] = a;
                p_scr[((size_t)t * BB + b) * DD + i] = pre;
            }
            __syncthreads();                               // B2: as ready

            // ---- dot2: s partials (half h handles as groups [half*16, half*16+16)) ----
            {
                int q0 = half << 4;
                float s0 = 0.f, s1 = 0.f;
                #pragma unroll
                for (int k4 = 0; k4 < 16; k4 += 2) {
                    s0 = dot4(WG4(96 + 4 * k4),     as4[q0 + k4],     s0);
                    s1 = dot4(WG4(96 + 4 * k4 + 4), as4[q0 + k4 + 1], s1);
                }
                part2[tid] = s0 + s1;
            }
            __syncthreads();                               // B3: s-partials ready

            if (half == 0) {
                float s = part2[i] + part2[i + 128];
                float g = sigmoid_xla_cpu(s);
                float h = hs[i];
                float c = (h - 1.0f) * g * (1.0f - g);
                float hn = __fadd_rn(__fmul_rn(g, h), __fsub_rn(1.0f, g));

                size_t o = ((size_t)t * BB + b) * DD + i;
                g_scr[o] = g;
                c_scr[o] = c;
                yrow[(size_t)t * DD + i] = hn;
                hs[i] = hn;
                if (pub) __threadfence();
            }
            if (pf) xsb[(((t + 1) & 1) << 6) + tid] = xpre;
            __syncthreads();                               // B4: hs/x published
            if (pub && tid == 0) progress[b] = t + 1;
        }

        if (half == 0) out[b * DD + i] = hs[i];

        // extra eval for dh_dWh (same split; x = x[:,T-1])
        {
            {
                const float4* xv4 = (const float4*)(xsb + (((TT - 1) & 1) << 6));
                float p0 = 0.f, p1 = 0.f;
                if (half == 0) {
                    #pragma unroll
                    for (int k4 = 0; k4 < 16; k4 += 2) {
                        p0 = dot4(WG4(4 * k4),     xv4[k4],     p0);
                        p1 = dot4(WG4(4 * k4 + 4), xv4[k4 + 1], p1);
                    }
                    #pragma unroll
                    for (int k4 = 0; k4 < 8; k4 += 2) {
                        p0 = dot4(WG4(64 + 4 * k4),     hs4[k4],     p0);
                        p1 = dot4(WG4(64 + 4 * k4 + 4), hs4[k4 + 1], p1);
                    }
                } else {
                    #pragma unroll
                    for (int k4 = 0; k4 < 24; k4 += 2) {
                        p0 = dot4(WG4(4 * k4),     hs4[8 + k4],     p0);
                        p1 = dot4(WG4(4 * k4 + 4), hs4[8 + k4 + 1], p1);
                    }
                }
                part[tid] = p0 + p1;
            }
            __syncthreads();
            if (half == 0) {
                float pre = part[i] + part[i + 128];
                float u_  = __fdiv_rn(pre, SQRT2);
                float er  = erf_xla_cpu(u_);
                float a   = __fmul_rn(__fmul_rn(pre, __fadd_rn(er, 1.0f)), 0.5f);
                float cdf = 0.5f * (1.0f + er);
                d2_scr[b * DD + i] = cdf + pre * 0.3989422804014327f * expf(-0.5f * pre * pre);
                as_[i] = a;
            }
            __syncthreads();
            {
                int q0 = half << 4;
                float s0 = 0.f, s1 = 0.f;
                #pragma unroll
                for (int k4 = 0; k4 < 16; k4 += 2) {
                    s0 = dot4(WG4(96 + 4 * k4),     as4[q0 + k4],     s0);
                    s1 = dot4(WG4(96 + 4 * k4 + 4), as4[q0 + k4 + 1], s1);
                }
                part2[tid] = s0 + s1;
            }
            __syncthreads();
            if (half == 0) {
                float s = part2[i] + part2[i + 128];
                float g = sigmoid_xla_cpu(s);
                float h = hs[i];
                c2_scr[b * DD + i] = (h - 1.0f) * g * (1.0f - g);
                __threadfence();
            }
        }
        __syncthreads();
        if (tid == 0) atomicAdd(&p1done_cnt, 1);
    } else {
        // ================= CONSUMER: phase 2 (unchanged) =================
        float* Wgs = sm;
        float* WhT = sm + DD * DD;
        float* ds  = WhT + DD * DD;
        float* cs  = ds + DD;
        float* gs  = cs + DD;
        int* rowlist = (int*)(gs + DD);

        for (int idx = tid; idx < DD * DD; idx += 256) Wgs[idx] = Wg[idx];
        for (int idx = tid; idx < DD * DD; idx += 256) {
            int j = idx / DD, k = idx % DD;
            WhT[k * DD + j] = Wh[idx];
        }

        const int ti = tid & 15, tj = tid >> 4;
        const int i0 = ti * 8, j0 = tj * 8;
        float* jbase = out + OUT_JAC;
        const int cid = bid - NPROD;

        for (int job = cid; job < TT * BB; job += NCONS) {
            const int b = job & (BB - 1);
            const int t = job >> 5;
            if (tid == 0) {
                while (progress[b] < t + 1) __nanosleep(64);
                __threadfence();
                cnt = 0;
            }
            __syncthreads();
            if (tid < DD) {
                size_t o = (size_t)job * DD + tid;
                float pre = __ldcg(&p_scr[o]);
                float cdf = 0.5f * (1.0f + erff(pre * 0.7071067811865476f));
                ds[tid] = cdf + pre * 0.3989422804014327f * expf(-0.5f * pre * pre);
                float c = __ldcg(&c_scr[o]);
                cs[tid] = c;
                gs[tid] = __ldcg(&g_scr[o]);
                if (c != 0.0f) { int p = atomicAdd(&cnt, 1); rowlist[p] = tid; }
            }
            __syncthreads();
            int n = cnt;
            float* jac = jbase + (size_t)job * (DD * DD);

            if (n > P2_THRESH) {
                float acc[8][8];
                #pragma unroll
                for (int a = 0; a < 8; a++)
                    #pragma unroll
                    for (int q = 0; q < 8; q++) acc[a][q] = 0.f;

                #pragma unroll 2
                for (int k = 0; k < DD; k++) {
                    float dk = ds[k];
                    float4 wa0 = *(const float4*)(Wgs + k * DD + i0);
                    float4 wa1 = *(const float4*)(Wgs + k * DD + i0 + 4);
                    float4 wb0 = *(const float4*)(WhT + k * DD + j0);
                    float4 wb1 = *(const float4*)(WhT + k * DD + j0 + 4);
                    float av[8] = {wa0.x * dk, wa0.y * dk, wa0.z * dk, wa0.w * dk,
                                   wa1.x * dk, wa1.y * dk, wa1.z * dk, wa1.w * dk};
                    float bv[8] = {wb0.x, wb0.y, wb0.z, wb0.w, wb1.x, wb1.y, wb1.z, wb1.w};
                    #pragma unroll
                    for (int a = 0; a < 8; a++)
                        #pragma unroll
                        for (int q = 0; q < 8; q++)
                            acc[a][q] = fmaf(av[a], bv[q], acc[a][q]);
                }

                #pragma unroll
                for (int a = 0; a < 8; a++) {
                    int irow = i0 + a;
                    float ci = cs[irow], gi = gs[irow];
                    float v[8];
                    #pragma unroll
                    for (int q = 0; q < 8; q++) {
                        float val = ci * acc[a][q];
                        if (irow == j0 + q) val += gi;
                        v[q] = val;
                    }
                    float* dst = jac + (size_t)irow * DD + j0;
                    *(float4*)(dst)     = make_float4(v[0], v[1], v[2], v[3]);
                    *(float4*)(dst + 4) = make_float4(v[4], v[5], v[6], v[7]);
                }
            } else {
                float4* j4 = (float4*)jac;
                #pragma unroll 4
                for (int idx = tid; idx < DD * DD / 4; idx += 256) {
                    int row = idx >> 5;
                    if (cs[row] == 0.0f) {
                        int c0 = (idx & 31) << 2;
                        float gv = gs[row];
                        float4 v;
                        v.x = (row == c0 + 0) ? gv : 0.f;
                        v.y = (row == c0 + 1) ? gv : 0.f;
                        v.z = (row == c0 + 2) ? gv : 0.f;
                        v.w = (row == c0 + 3) ? gv : 0.f;
                        j4[idx] = v;
                    }
                }
                for (int r = 0; r < n; r += 2) {
                    int rr = r + (tid >> 7);
                    if (rr < n) {
                        int irow = rowlist[rr];
                        int j = tid & 127;
                        float a0 = 0.f, a1 = 0.f;
                        #pragma unroll 4
                        for (int k = 0; k < DD; k += 2) {
                            a0 = fmaf(ds[k]     * Wgs[k * DD + irow],       WhT[k * DD + j],       a0);
                            a1 = fmaf(ds[k + 1] * Wgs[(k + 1) * DD + irow], WhT[(k + 1) * DD + j], a1);
                        }
                        float val = cs[irow] * (a0 + a1);
                        if (irow == j) val += gs[irow];
                        jac[(size_t)irow * DD + j] = val;
                    }
                }
            }
        }
    }

    // ================= TAIL: phase 3 (all blocks) =================
    __syncthreads();
    if (tid == 0) {
        while (*(volatile int*)&p1done_cnt < NPROD) __nanosleep(128);
        __threadfence();
    }
    __syncthreads();

    for (int bi = bid; bi < BB * DD; bi += NSM) {
        const int b = bi >> 7, i = bi & 127;
        if (tid < DD) {
            float c2 = __ldcg(&c2_scr[b * DD + i]);
            vs[tid]  = c2 * __ldcg(&d2_scr[b * DD + tid]) * Wg[tid * DD + i];
            hsh[tid] = __ldcg(&out[b * DD + tid]);
        }
        __syncthreads();
        float4* dst = (float4*)(out + OUT_DWH + (size_t)bi * DD * DD);
        const float4* vs4 = (const float4*)vs;
        #pragma unroll 4
        for (int idx = tid; idx < DD * DD / 4; idx += 256) {
            int p  = idx >> 5;
            int q4 = idx & 31;
            float hp = hsh[p];
            float4 v = vs4[q4];
            dst[idx] = make_float4(v.x * hp, v.y * hp, v.z * hp, v.w * hp);
        }
        __syncthreads();
    }
}

extern "C" void kernel_launch(void* const* d_in, const int* in_sizes, int n_in,
                              void* d_out, int out_size) {
    const float* x  = (const float*)d_in[0];
    const float* h0 = (const float*)d_in[1];
    const float* Wx = (const float*)d_in[2];
    const float* Wg = (const float*)d_in[3];
    const float* Wh = (const float*)d_in[4];
    float* out = (float*)d_out;

    cudaFuncSetAttribute(fused_kernel, cudaFuncAttributeMaxDynamicSharedMemorySize, FUSED_SMEM_BYTES);

    reset_kernel<<<1, 64>>>();
    fused_kernel<<<NSM, 256, FUSED_SMEM_BYTES>>>(x, h0, Wx, Wg, Wh, out);
}